// round 15
// baseline (speedup 1.0000x reference)
#include <cuda_runtime.h>
#include <cuda_fp16.h>
#include <cstdint>

#define BB 64
#define NN 64
#define FA 75
#define FP 14
#define CC 128
#define NROWS_A (BB*NN)
#define ATOM_OUT (BB*NN*CC)

// ---------------- global scratch ----------------
__device__ float g_U [NROWS_A*CC];
__device__ float g_V [NROWS_A*CC];
__device__ float g_a0[NROWS_A*CC];
__device__ float g_a1[NROWS_A*CC];
__device__ __align__(16) __half g_R0[(size_t)BB*NN*NN*CC];   // relu(y0+b1a), 64 MB

// transposed ([N=128][K]) fp16, zero-padded weights
__device__ __align__(16) __half g_Wp2a0[128*16];
__device__ __align__(16) __half g_Wp2a1[128*128];
__device__ __align__(16) __half g_Wp2p0[128*16];
__device__ __align__(16) __half g_Wp2p1[128*128];
__device__ __align__(16) __half g_Wa2p1[128*128];
__device__ __align__(16) __half g_Wpl0a[128*128];
__device__ __align__(16) __half g_Wpl0b[128*128];
__device__ __align__(16) __half g_Wpl1 [128*128];
__device__ __align__(16) __half g_Wal0a[128*128];
__device__ __align__(16) __half g_Wal0b[128*128];
__device__ __align__(16) __half g_Wal1 [128*128];
__device__ __align__(16) __half g_Wa2a0 [128*80];
__device__ __align__(16) __half g_Wa2a1 [128*128];
__device__ __align__(16) __half g_Wa2p0a[128*80];
__device__ __align__(16) __half g_Wa2p0b[128*80];

// ---------------- helpers ----------------
__device__ __forceinline__ uint32_t smem_u32(const void* p){
    uint32_t a;
    asm("{ .reg .u64 t; cvta.to.shared.u64 t, %1; cvt.u32.u64 %0, t; }" : "=r"(a) : "l"(p));
    return a;
}
__device__ __forceinline__ void mma_f16(float c[4], const uint32_t a[4], const uint32_t b[2]){
    asm volatile("mma.sync.aligned.m16n8k16.row.col.f32.f16.f16.f32 "
        "{%0,%1,%2,%3}, {%4,%5,%6,%7}, {%8,%9}, {%0,%1,%2,%3};"
        : "+f"(c[0]), "+f"(c[1]), "+f"(c[2]), "+f"(c[3])
        : "r"(a[0]), "r"(a[1]), "r"(a[2]), "r"(a[3]), "r"(b[0]), "r"(b[1]));
}
__device__ __forceinline__ void ldsm4(uint32_t* r, uint32_t addr){
    asm volatile("ldmatrix.sync.aligned.m8n8.x4.shared.b16 {%0,%1,%2,%3}, [%4];"
        : "=r"(r[0]), "=r"(r[1]), "=r"(r[2]), "=r"(r[3]) : "r"(addr));
}

#define CP_COMMIT asm volatile("cp.async.commit_group;" ::: "memory")
#define CP_WAIT0  asm volatile("cp.async.wait_group 0;" ::: "memory")
#define CP_WAIT1  asm volatile("cp.async.wait_group 1;" ::: "memory")

// async copy [128][K] half gmem -> smem (stride ld halves), NT threads
__device__ __forceinline__ void cpa_h(__half* dstS, const __half* src, int K, int ld,
                                      int tid, int NT){
    size_t gp = __cvta_generic_to_global(src);
    uint32_t base = smem_u32(dstS);
    int ch = K >> 3;
    int tot = 128 * ch;
    for (int i = tid; i < tot; i += NT){
        int n = i / ch, c = i - n * ch;
        uint32_t d = base + (uint32_t)(n * ld + c * 8) * 2u;
        asm volatile("cp.async.ca.shared.global [%0], [%1], 16;" :: "r"(d), "l"(gp + (size_t)i * 16) : "memory");
    }
    CP_COMMIT;
}

// ---- LDSM warp GEMM: warp tile (MF*16) x (NF*8) ----
template<int KSTEPS, int MF, int NF>
__device__ __forceinline__ void wg_ldsm(float (&acc)[MF][NF][4],
        uint32_t Asa, int lda, uint32_t Bsa, int ldb,
        int wrow, int wcol, int lane){
    const int t = lane >> 3, tr = lane & 7;
    uint32_t aA[MF], aB[NF/2];
#pragma unroll
    for (int mf = 0; mf < MF; ++mf)
        aA[mf] = Asa + (uint32_t)((wrow + mf * 16 + (t & 1) * 8 + tr) * lda + (t >> 1) * 8) * 2u;
#pragma unroll
    for (int p = 0; p < NF / 2; ++p)
        aB[p] = Bsa + (uint32_t)((wcol + (2 * p + (t >> 1)) * 8 + tr) * ldb + (t & 1) * 8) * 2u;
#pragma unroll
    for (int ks = 0; ks < KSTEPS; ++ks){
        uint32_t a[MF][4], b[NF][2];
#pragma unroll
        for (int mf = 0; mf < MF; ++mf) ldsm4(a[mf], aA[mf] + ks * 32);
#pragma unroll
        for (int p = 0; p < NF / 2; ++p) ldsm4(&b[2 * p][0], aB[p] + ks * 32);
#pragma unroll
        for (int mf = 0; mf < MF; ++mf)
#pragma unroll
            for (int nf = 0; nf < NF; ++nf)
                mma_f16(acc[mf][nf], a[mf], b[nf]);
    }
}

template<int MF, int NF>
__device__ __forceinline__ void zacc(float (&a)[MF][NF][4]){
#pragma unroll
    for (int m = 0; m < MF; ++m)
#pragma unroll
        for (int n = 0; n < NF; ++n)
#pragma unroll
            for (int q = 0; q < 4; ++q) a[m][n][q] = 0.f;
}

// relu(acc + bias) -> half smem (stride ldd halves)
template<int MF, int NF>
__device__ __forceinline__ void epi_smem_h(const float (&acc)[MF][NF][4], __half* dst, int ldd,
        const float* __restrict__ bias, int wrow, int wcol, int lane){
    int r0 = wrow + (lane >> 2);
    int c0 = wcol + 2 * (lane & 3);
#pragma unroll
    for (int mf = 0; mf < MF; ++mf)
#pragma unroll
        for (int nf = 0; nf < NF; ++nf){
            int c = c0 + nf * 8;
            float bx = bias[c], by = bias[c + 1];
            int ra = r0 + mf * 16, rb = ra + 8;
            *(__half2*)(dst + ra * ldd + c) =
                __floats2half2_rn(fmaxf(acc[mf][nf][0] + bx, 0.f), fmaxf(acc[mf][nf][1] + by, 0.f));
            *(__half2*)(dst + rb * ldd + c) =
                __floats2half2_rn(fmaxf(acc[mf][nf][2] + bx, 0.f), fmaxf(acc[mf][nf][3] + by, 0.f));
        }
}

// relu(acc + bias) -> gmem fp32 tile (stride 128)
template<int MF, int NF>
__device__ __forceinline__ void epi_gmem_relu(const float (&acc)[MF][NF][4], float* __restrict__ dst,
        const float* __restrict__ bias, int wrow, int wcol, int lane){
    int r0 = wrow + (lane >> 2);
    int c0 = wcol + 2 * (lane & 3);
#pragma unroll
    for (int mf = 0; mf < MF; ++mf)
#pragma unroll
        for (int nf = 0; nf < NF; ++nf){
            int c = c0 + nf * 8;
            float bx = bias[c], by = bias[c + 1];
            int ra = r0 + mf * 16, rb = ra + 8;
            *(float2*)(dst + ra * 128 + c) = make_float2(fmaxf(acc[mf][nf][0] + bx, 0.f),
                                                         fmaxf(acc[mf][nf][1] + by, 0.f));
            *(float2*)(dst + rb * 128 + c) = make_float2(fmaxf(acc[mf][nf][2] + bx, 0.f),
                                                         fmaxf(acc[mf][nf][3] + by, 0.f));
        }
}
// relu(acc + bias) -> gmem fp16 tile (stride 128)
template<int MF, int NF>
__device__ __forceinline__ void epi_gmem_relu_h(const float (&acc)[MF][NF][4], __half* __restrict__ dst,
        const float* __restrict__ bias, int wrow, int wcol, int lane){
    int r0 = wrow + (lane >> 2);
    int c0 = wcol + 2 * (lane & 3);
#pragma unroll
    for (int mf = 0; mf < MF; ++mf)
#pragma unroll
        for (int nf = 0; nf < NF; ++nf){
            int c = c0 + nf * 8;
            float bx = bias[c], by = bias[c + 1];
            int ra = r0 + mf * 16, rb = ra + 8;
            *(__half2*)(dst + ra * 128 + c) =
                __floats2half2_rn(fmaxf(acc[mf][nf][0] + bx, 0.f), fmaxf(acc[mf][nf][1] + by, 0.f));
            *(__half2*)(dst + rb * 128 + c) =
                __floats2half2_rn(fmaxf(acc[mf][nf][2] + bx, 0.f), fmaxf(acc[mf][nf][3] + by, 0.f));
        }
}
template<int MF, int NF>
__device__ __forceinline__ void epi_gmem_raw(const float (&acc)[MF][NF][4], float* __restrict__ dst,
        int wrow, int wcol, int lane){
    int r0 = wrow + (lane >> 2);
    int c0 = wcol + 2 * (lane & 3);
#pragma unroll
    for (int mf = 0; mf < MF; ++mf)
#pragma unroll
        for (int nf = 0; nf < NF; ++nf){
            int c = c0 + nf * 8;
            int ra = r0 + mf * 16, rb = ra + 8;
            *(float2*)(dst + ra * 128 + c) = make_float2(acc[mf][nf][0], acc[mf][nf][1]);
            *(float2*)(dst + rb * 128 + c) = make_float2(acc[mf][nf][2], acc[mf][nf][3]);
        }
}

// ---------------- weight prep ----------------
__device__ __forceinline__ void wprep(__half* dst, const float* src, int Kpad, int Ksrc, int tid){
    for (int i = tid; i < 128 * Kpad; i += 256){
        int n = i / Kpad, k = i - n * Kpad;
        dst[i] = __float2half_rn(k < Ksrc ? src[k * 128 + n] : 0.f);
    }
}
extern "C" __global__ void kW(const float* __restrict__ p2aW0, const float* __restrict__ p2aW1,
                              const float* __restrict__ p2pW0, const float* __restrict__ p2pW1,
                              const float* __restrict__ a2pW1, const float* __restrict__ plW0,
                              const float* __restrict__ plW1,  const float* __restrict__ alW0,
                              const float* __restrict__ alW1,  const float* __restrict__ a2aW0,
                              const float* __restrict__ a2aW1, const float* __restrict__ a2pW0){
    int t = blockIdx.x, tid = threadIdx.x;
    switch (t){
        case 0:  wprep(g_Wp2a0,  p2aW0,            16, FP,  tid); break;
        case 1:  wprep(g_Wp2a1,  p2aW1,           128, 128, tid); break;
        case 2:  wprep(g_Wp2p0,  p2pW0,            16, FP,  tid); break;
        case 3:  wprep(g_Wp2p1,  p2pW1,           128, 128, tid); break;
        case 4:  wprep(g_Wa2p1,  a2pW1,           128, 128, tid); break;
        case 5:  wprep(g_Wpl0a,  plW0,            128, 128, tid); break;
        case 6:  wprep(g_Wpl0b,  plW0 + 128*128,  128, 128, tid); break;
        case 7:  wprep(g_Wpl1,   plW1,            128, 128, tid); break;
        case 8:  wprep(g_Wal0a,  alW0,            128, 128, tid); break;
        case 9:  wprep(g_Wal0b,  alW0 + 128*128,  128, 128, tid); break;
        case 10: wprep(g_Wal1,   alW1,            128, 128, tid); break;
        case 11: wprep(g_Wa2a0,  a2aW0,            80, FA,  tid); break;
        case 12: wprep(g_Wa2a1,  a2aW1,           128, 128, tid); break;
        case 13: wprep(g_Wa2p0a, a2pW0,            80, FA,  tid); break;
        default: wprep(g_Wa2p0b, a2pW0 + FA*128,   80, FA,  tid); break;
    }
}

// ---------------- kernel A: atom precompute (R8-proven) ----------------
extern "C" __global__ void __launch_bounds__(256, 1)
kA(const float* __restrict__ atom_x,
   const float* __restrict__ a2a_b0, const float* __restrict__ a2a_b1){
    extern __shared__ __half smh[];
    __half* As  = smh;                    // 128*136
    __half* act = As + 128 * 136;         // 128*136
    __half* Bw  = act + 128 * 136;        // 128*136
    int tid = threadIdx.x, lane = tid & 31, w = tid >> 5;
    int wr = (w & 1) * 64, wc = (w >> 1) * 32;
    int blk = blockIdx.x, task = blockIdx.y;
    uint32_t As_a = smem_u32(As), act_a = smem_u32(act), Bw_a = smem_u32(Bw);

    const __half* w0 = (task == 0) ? g_Wa2a0 : (task == 1 ? g_Wa2p0a : g_Wa2p0b);
    cpa_h(Bw, w0, 80, 136, tid, 256);
    for (int i = tid; i < 128 * 80; i += 256){
        int r = i / 80, k = i - r * 80;
        float v = (k < FA) ? atom_x[(blk * 128 + r) * FA + k] : 0.f;
        As[r * 136 + k] = __float2half_rn(v);
    }
    CP_WAIT0;
    __syncthreads();

    float acc[4][4][4];
    zacc(acc);
    wg_ldsm<5, 4, 4>(acc, As_a, 136, Bw_a, 136, wr, wc, lane);
    if (task == 0){
        __syncthreads();
        cpa_h(Bw, g_Wa2a1, 128, 136, tid, 256);
        epi_smem_h<4,4>(acc, act, 136, a2a_b0, wr, wc, lane);
        CP_WAIT0;
        __syncthreads();
        zacc(acc);
        wg_ldsm<8, 4, 4>(acc, act_a, 136, Bw_a, 136, wr, wc, lane);
        epi_gmem_relu<4,4>(acc, g_a0 + blk * 16384, a2a_b1, wr, wc, lane);
    } else {
        float* dst = (task == 1 ? g_U : g_V) + blk * 16384;
        epi_gmem_raw<4,4>(acc, dst, wr, wc, lane);
    }
}

// ---------------- kernel B1: p2a branch + a1 + y0 -> g_R0 ----------------
// grid 2048: CTA per (b,i2); rows r: ih = 2*i2 + (r>>6), j = r&63.
// smem: actA 128*136 | Bw 128*136 | pxs 128*24  (=75776 B, 2 CTAs/SM)
extern "C" __global__ void __launch_bounds__(256, 2)
kB1(const float* __restrict__ pair_x,
    const float* __restrict__ p2a_b0, const float* __restrict__ p2a_b1,
    const float* __restrict__ a2p_b0, const float* __restrict__ a2p_b1){
    extern __shared__ __half smh[];
    __half* actA = smh;                   // 128*136
    __half* Bw   = actA + 128 * 136;      // 128*136
    __half* pxs  = Bw + 128 * 136;        // 128*24
    int tid = threadIdx.x, lane = tid & 31, w = tid >> 5;
    int wm = w & 1;
    int wr = wm * 64, wc = (w >> 1) * 32;
    int cta = blockIdx.x;
    int b = cta >> 5, i2 = cta & 31;
    size_t tilebase = (size_t)b * 4096 + (size_t)i2 * 128;
    const float* gU = g_U + b * 8192;
    const float* gV = g_V + b * 8192;
    uint32_t actA_a = smem_u32(actA), Bw_a = smem_u32(Bw), pxs_a = smem_u32(pxs);

    float acc[4][4][4];

    // ---- prologue ----
    cpa_h(Bw, g_Wp2a0, 16, 24, tid, 256);
    for (int i = tid; i < 128 * 16; i += 256){
        int r = i >> 4, k = i & 15;
        float v = (k < FP) ? pair_x[(tilebase + r) * FP + k] : 0.f;
        pxs[r * 24 + k] = __float2half_rn(v);
    }
    CP_WAIT0;
    __syncthreads();

    // ---- G1: px @ p2aW0 ----
    zacc(acc);
    wg_ldsm<1, 4, 4>(acc, pxs_a, 24, Bw_a, 24, wr, wc, lane);
    __syncthreads();
    cpa_h(Bw, g_Wp2a1, 128, 136, tid, 256);
    epi_smem_h<4,4>(acc, actA, 136, p2a_b0, wr, wc, lane);
    CP_WAIT0;
    __syncthreads();

    // ---- G2: actA @ p2aW1 ; epi = relu + column-sum -> g_a1 ; build h0 -> actA ----
    zacc(acc);
    wg_ldsm<8, 4, 4>(acc, actA_a, 136, Bw_a, 136, wr, wc, lane);
    __syncthreads();
    cpa_h(Bw, g_Wa2p1, 128, 136, tid, 256);
    {
        int c0 = wc + 2 * (lane & 3);
#pragma unroll
        for (int nf = 0; nf < 4; ++nf){
            int c = c0 + nf * 8;
            float bx = p2a_b1[c], by = p2a_b1[c + 1];
            float s0 = 0.f, s1 = 0.f;
#pragma unroll
            for (int mf = 0; mf < 4; ++mf){
                s0 += fmaxf(acc[mf][nf][0] + bx, 0.f) + fmaxf(acc[mf][nf][2] + bx, 0.f);
                s1 += fmaxf(acc[mf][nf][1] + by, 0.f) + fmaxf(acc[mf][nf][3] + by, 0.f);
            }
#pragma unroll
            for (int off = 4; off < 32; off <<= 1){
                s0 += __shfl_xor_sync(0xFFFFFFFFu, s0, off);
                s1 += __shfl_xor_sync(0xFFFFFFFFu, s1, off);
            }
            if (lane < 4){
                float* gr = g_a1 + ((size_t)b * 64 + i2 * 2 + wm) * 128 + c;
                gr[0] = s0; gr[1] = s1;
            }
        }
    }
    for (int i = tid; i < 128 * 32; i += 256){      // h0 = relu(U[ih] + V[j] + b0a)
        int r = i >> 5, c4 = (i & 31) << 2;
        int ih = i2 * 2 + (r >> 6), j = r & 63;
        float4 uu = *(const float4*)(gU + ih * 128 + c4);
        float4 vv = *(const float4*)(gV + j  * 128 + c4);
        float4 bb = *(const float4*)(a2p_b0 + c4);
        *(__half2*)(actA + r * 136 + c4)     = __floats2half2_rn(fmaxf(uu.x + vv.x + bb.x, 0.f),
                                                                 fmaxf(uu.y + vv.y + bb.y, 0.f));
        *(__half2*)(actA + r * 136 + c4 + 2) = __floats2half2_rn(fmaxf(uu.z + vv.z + bb.z, 0.f),
                                                                 fmaxf(uu.w + vv.w + bb.w, 0.f));
    }
    CP_WAIT0;
    __syncthreads();

    // ---- G3: h0 @ a2pW1 (y0) ; epi: R0 = relu(y0 + b1a) -> gmem fp16 ----
    zacc(acc);
    wg_ldsm<8, 4, 4>(acc, actA_a, 136, Bw_a, 136, wr, wc, lane);
    epi_gmem_relu_h<4,4>(acc, g_R0 + tilebase * 128, a2p_b1, wr, wc, lane);
}

// ---------------- kernel B2: p0 = R0 + R0^T ; p2p ; pair layer -> out ----------------
// grid 2048: CTA per (b,i2). smem: actA | actB | Bw | pxs  (=110592 B, 2 CTAs/SM)
extern "C" __global__ void __launch_bounds__(256, 2)
kB2(const float* __restrict__ pair_x,
    const float* __restrict__ p2p_b0, const float* __restrict__ p2p_b1,
    const float* __restrict__ pl_b0,  const float* __restrict__ pl_b1,
    float* __restrict__ out_pair){
    extern __shared__ __half smh[];
    __half* actA = smh;                   // 128*136
    __half* actB = actA + 128 * 136;      // 128*136
    __half* Bw   = actB + 128 * 136;      // 128*136
    __half* pxs  = Bw + 128 * 136;        // 128*24
    int tid = threadIdx.x, lane = tid & 31, w = tid >> 5;
    int wr = (w & 1) * 64, wc = (w >> 1) * 32;
    int cta = blockIdx.x;
    int b = cta >> 5, i2 = cta & 31;
    size_t tilebase = (size_t)b * 4096 + (size_t)i2 * 128;
    uint32_t actA_a = smem_u32(actA), actB_a = smem_u32(actB), Bw_a = smem_u32(Bw);
    uint32_t pxs_a = smem_u32(pxs);

    float acc[4][4][4];

    // ---- prologue ----
    cpa_h(Bw, g_Wp2p0, 16, 24, tid, 256);
    for (int i = tid; i < 128 * 16; i += 256){
        int r = i >> 4, k = i & 15;
        float v = (k < FP) ? pair_x[(tilebase + r) * FP + k] : 0.f;
        pxs[r * 24 + k] = __float2half_rn(v);
    }
    CP_WAIT0;
    __syncthreads();

    // ---- G5: px @ p2pW0 ; post: epi->actA AND build p0 -> actB ----
    zacc(acc);
    wg_ldsm<1, 4, 4>(acc, pxs_a, 24, Bw_a, 24, wr, wc, lane);
    __syncthreads();
    cpa_h(Bw, g_Wp2p1, 128, 136, tid, 256);
    epi_smem_h<4,4>(acc, actA, 136, p2p_b0, wr, wc, lane);
    {   // p0(ih,j) = R0(ih,j) + R0(j,ih)  -> actB  (half2 granularity)
        const __half2* R0d = (const __half2*)(g_R0 + tilebase * 128);
        for (int i = tid; i < 128 * 64; i += 256){
            int r = i >> 6, cc = i & 63;
            int ih = i2 * 2 + (r >> 6), j = r & 63;
            __half2 d = R0d[(size_t)r * 64 + cc];
            __half2 tshalf = *(const __half2*)(g_R0 + ((size_t)b * 4096 + (size_t)j * 64 + ih) * 128 + cc * 2);
            float2 fd = __half22float2(d), ft = __half22float2(tshalf);
            *(__half2*)(actB + r * 136 + cc * 2) = __floats2half2_rn(fd.x + ft.x, fd.y + ft.y);
        }
    }
    CP_WAIT0;
    __syncthreads();

    // ---- G6: actA @ p2pW1 ; epi relu -> actA = p1 ----
    zacc(acc);
    wg_ldsm<8, 4, 4>(acc, actA_a, 136, Bw_a, 136, wr, wc, lane);
    __syncthreads();
    cpa_h(Bw, g_Wpl0b, 128, 136, tid, 256);
    epi_smem_h<4,4>(acc, actA, 136, p2p_b1, wr, wc, lane);
    CP_WAIT0;
    __syncthreads();

    // ---- G7: p1 @ plW0b (no epilogue) ----
    zacc(acc);
    wg_ldsm<8, 4, 4>(acc, actA_a, 136, Bw_a, 136, wr, wc, lane);
    __syncthreads();
    cpa_h(Bw, g_Wpl0a, 128, 136, tid, 256);
    CP_WAIT0;
    __syncthreads();

    // ---- G8: acc += p0 @ plW0a ; epi relu -> actA ----
    wg_ldsm<8, 4, 4>(acc, actB_a, 136, Bw_a, 136, wr, wc, lane);
    __syncthreads();
    cpa_h(Bw, g_Wpl1, 128, 136, tid, 256);
    epi_smem_h<4,4>(acc, actA, 136, pl_b0, wr, wc, lane);
    CP_WAIT0;
    __syncthreads();

    // ---- G9: actA @ plW1 -> out ----
    zacc(acc);
    wg_ldsm<8, 4, 4>(acc, actA_a, 136, Bw_a, 136, wr, wc, lane);
    epi_gmem_relu<4,4>(acc, out_pair + tilebase * 128, pl_b1, wr, wc, lane);
}

// ---------------- kernel C: atom finalize, grid 128 (M=32 per CTA) ----------------
extern "C" __global__ void __launch_bounds__(256, 2)
kC(const float* __restrict__ al_b0, const float* __restrict__ al_b1,
   float* __restrict__ out_atom){
    extern __shared__ __half smh[];
    __half* As  = smh;                    // 32*136
    __half* Bw0 = As + 32 * 136;          // 128*136
    __half* Bw1 = Bw0 + 128 * 136;        // 128*136
    int tid = threadIdx.x, lane = tid & 31, w = tid >> 5;
    int blk = blockIdx.x;
    int base = (blk >> 1) * 8192 + (blk & 1) * 4096;
    uint32_t As_a = smem_u32(As), B0_a = smem_u32(Bw0), B1_a = smem_u32(Bw1);
    const int wc = w * 16;

    cpa_h(Bw0, g_Wal0a, 128, 136, tid, 256);
    cpa_h(Bw1, g_Wal0b, 128, 136, tid, 256);
    for (int i = tid; i < 32 * 32; i += 256){
        int r = i >> 5, c4 = (i & 31) << 2;
        float4 v = *(const float4*)(g_a0 + base + r * 128 + c4);
        *(__half2*)(As + r * 136 + c4)     = __floats2half2_rn(v.x, v.y);
        *(__half2*)(As + r * 136 + c4 + 2) = __floats2half2_rn(v.z, v.w);
    }
    CP_WAIT1;
    __syncthreads();

    float acc[2][2][4];
    zacc(acc);
    wg_ldsm<8, 2, 2>(acc, As_a, 136, B0_a, 136, 0, wc, lane);
    __syncthreads();
    cpa_h(Bw0, g_Wal1, 128, 136, tid, 256);
    for (int i = tid; i < 32 * 32; i += 256){
        int r = i >> 5, c4 = (i & 31) << 2;
        float4 v = *(const float4*)(g_a1 + base + r * 128 + c4);
        *(__half2*)(As + r * 136 + c4)     = __floats2half2_rn(v.x, v.y);
        *(__half2*)(As + r * 136 + c4 + 2) = __floats2half2_rn(v.z, v.w);
    }
    CP_WAIT1;
    __syncthreads();

    wg_ldsm<8, 2, 2>(acc, As_a, 136, B1_a, 136, 0, wc, lane);
    __syncthreads();
    epi_smem_h<2,2>(acc, As, 136, al_b0, 0, wc, lane);
    CP_WAIT0;
    __syncthreads();

    zacc(acc);
    wg_ldsm<8, 2, 2>(acc, As_a, 136, B0_a, 136, 0, wc, lane);
    epi_gmem_relu<2,2>(acc, out_atom + base, al_b1, 0, wc, lane);
}

// ---------------------------------------------------------------------------
extern "C" void kernel_launch(void* const* d_in, const int* in_sizes, int n_in,
                              void* d_out, int out_size) {
    const float* atom_x = (const float*)d_in[0];
    const float* pair_x = (const float*)d_in[1];
    const float* a2a_W0 = (const float*)d_in[2];
    const float* a2a_b0 = (const float*)d_in[3];
    const float* a2a_W1 = (const float*)d_in[4];
    const float* a2a_b1 = (const float*)d_in[5];
    const float* p2a_W0 = (const float*)d_in[6];
    const float* p2a_b0 = (const float*)d_in[7];
    const float* p2a_W1 = (const float*)d_in[8];
    const float* p2a_b1 = (const float*)d_in[9];
    const float* al_W0  = (const float*)d_in[10];
    const float* al_b0  = (const float*)d_in[11];
    const float* al_W1  = (const float*)d_in[12];
    const float* al_b1  = (const float*)d_in[13];
    const float* a2p_W0 = (const float*)d_in[14];
    const float* a2p_b0 = (const float*)d_in[15];
    const float* a2p_W1 = (const float*)d_in[16];
    const float* a2p_b1 = (const float*)d_in[17];
    const float* p2p_W0 = (const float*)d_in[18];
    const float* p2p_b0 = (const float*)d_in[19];
    const float* p2p_W1 = (const float*)d_in[20];
    const float* p2p_b1 = (const float*)d_in[21];
    const float* pl_W0  = (const float*)d_in[22];
    const float* pl_b0  = (const float*)d_in[23];
    const float* pl_W1  = (const float*)d_in[24];
    const float* pl_b1  = (const float*)d_in[25];
    float* out = (float*)d_out;

    const int SMEM_A  = (3 * 128 * 136) * 2;                 // 104448 B
    const int SMEM_B1 = (2 * 128 * 136 + 128 * 24) * 2;      // 75776 B
    const int SMEM_B2 = (3 * 128 * 136 + 128 * 24) * 2;      // 110592 B
    const int SMEM_C  = (32 * 136 + 2 * 128 * 136) * 2;      // 78336 B

    cudaFuncSetAttribute(kA,  cudaFuncAttributeMaxDynamicSharedMemorySize, SMEM_A);
    cudaFuncSetAttribute(kB1, cudaFuncAttributeMaxDynamicSharedMemorySize, SMEM_B1);
    cudaFuncSetAttribute(kB2, cudaFuncAttributeMaxDynamicSharedMemorySize, SMEM_B2);
    cudaFuncSetAttribute(kC,  cudaFuncAttributeMaxDynamicSharedMemorySize, SMEM_C);

    kW<<<15, 256>>>(p2a_W0, p2a_W1, p2p_W0, p2p_W1, a2p_W1, pl_W0, pl_W1,
                    al_W0, al_W1, a2a_W0, a2a_W1, a2p_W0);
    kA<<<dim3(32, 3), 256, SMEM_A>>>(atom_x, a2a_b0, a2a_b1);
    kB1<<<2048, 256, SMEM_B1>>>(pair_x, p2a_b0, p2a_b1, a2p_b0, a2p_b1);
    kB2<<<2048, 256, SMEM_B2>>>(pair_x, p2p_b0, p2p_b1, pl_b0, pl_b1,
                                out + ATOM_OUT);
    kC<<<128, 256, SMEM_C>>>(al_b0, al_b1, out);
}

// round 17
// speedup vs baseline: 1.0855x; 1.0855x over previous
#include <cuda_runtime.h>
#include <cuda_fp16.h>
#include <cstdint>

#define BB 64
#define NN 64
#define FA 75
#define FP 14
#define CC 128
#define NROWS_A (BB*NN)
#define ATOM_OUT (BB*NN*CC)

// ---------------- global scratch ----------------
__device__ float g_U [NROWS_A*CC];
__device__ float g_V [NROWS_A*CC];
__device__ float g_a0[NROWS_A*CC];
__device__ float g_a1[NROWS_A*CC];

// transposed ([N=128][K]) fp16, zero-padded weights
__device__ __align__(16) __half g_Wp2a0[128*16];
__device__ __align__(16) __half g_Wp2a1[128*128];
__device__ __align__(16) __half g_Wp2p0[128*16];
__device__ __align__(16) __half g_Wp2p1[128*128];
__device__ __align__(16) __half g_Wa2p1[128*128];
__device__ __align__(16) __half g_Wpl0a[128*128];
__device__ __align__(16) __half g_Wpl0b[128*128];
__device__ __align__(16) __half g_Wpl1 [128*128];
__device__ __align__(16) __half g_Wal0a[128*128];
__device__ __align__(16) __half g_Wal0b[128*128];
__device__ __align__(16) __half g_Wal1 [128*128];
__device__ __align__(16) __half g_Wa2a0 [128*80];
__device__ __align__(16) __half g_Wa2a1 [128*128];
__device__ __align__(16) __half g_Wa2p0a[128*80];
__device__ __align__(16) __half g_Wa2p0b[128*80];

// ---------------- helpers ----------------
__device__ __forceinline__ uint32_t smem_u32(const void* p){
    uint32_t a;
    asm("{ .reg .u64 t; cvta.to.shared.u64 t, %1; cvt.u32.u64 %0, t; }" : "=r"(a) : "l"(p));
    return a;
}
__device__ __forceinline__ void mma_f16(float c[4], const uint32_t a[4], const uint32_t b[2]){
    asm volatile("mma.sync.aligned.m16n8k16.row.col.f32.f16.f16.f32 "
        "{%0,%1,%2,%3}, {%4,%5,%6,%7}, {%8,%9}, {%0,%1,%2,%3};"
        : "+f"(c[0]), "+f"(c[1]), "+f"(c[2]), "+f"(c[3])
        : "r"(a[0]), "r"(a[1]), "r"(a[2]), "r"(a[3]), "r"(b[0]), "r"(b[1]));
}
__device__ __forceinline__ void ldsm4(uint32_t* r, uint32_t addr){
    asm volatile("ldmatrix.sync.aligned.m8n8.x4.shared.b16 {%0,%1,%2,%3}, [%4];"
        : "=r"(r[0]), "=r"(r[1]), "=r"(r[2]), "=r"(r[3]) : "r"(addr));
}

#define CP_COMMIT asm volatile("cp.async.commit_group;" ::: "memory")
#define CP_WAIT0  asm volatile("cp.async.wait_group 0;" ::: "memory")
#define CP_WAIT1  asm volatile("cp.async.wait_group 1;" ::: "memory")

// async copy [128][K] half gmem -> smem (stride ld halves), NT threads
__device__ __forceinline__ void cpa_h(__half* dstS, const __half* src, int K, int ld,
                                      int tid, int NT){
    size_t gp = __cvta_generic_to_global(src);
    uint32_t base = smem_u32(dstS);
    int ch = K >> 3;
    int tot = 128 * ch;
    for (int i = tid; i < tot; i += NT){
        int n = i / ch, c = i - n * ch;
        uint32_t d = base + (uint32_t)(n * ld + c * 8) * 2u;
        asm volatile("cp.async.ca.shared.global [%0], [%1], 16;" :: "r"(d), "l"(gp + (size_t)i * 16) : "memory");
    }
    CP_COMMIT;
}

// ---- LDSM warp GEMM: warp tile (MF*16) x (NF*8) ----
template<int KSTEPS, int MF, int NF>
__device__ __forceinline__ void wg_ldsm(float (&acc)[MF][NF][4],
        uint32_t Asa, int lda, uint32_t Bsa, int ldb,
        int wrow, int wcol, int lane){
    const int t = lane >> 3, tr = lane & 7;
    uint32_t aA[MF], aB[NF/2];
#pragma unroll
    for (int mf = 0; mf < MF; ++mf)
        aA[mf] = Asa + (uint32_t)((wrow + mf * 16 + (t & 1) * 8 + tr) * lda + (t >> 1) * 8) * 2u;
#pragma unroll
    for (int p = 0; p < NF / 2; ++p)
        aB[p] = Bsa + (uint32_t)((wcol + (2 * p + (t >> 1)) * 8 + tr) * ldb + (t & 1) * 8) * 2u;
#pragma unroll
    for (int ks = 0; ks < KSTEPS; ++ks){
        uint32_t a[MF][4], b[NF][2];
#pragma unroll
        for (int mf = 0; mf < MF; ++mf) ldsm4(a[mf], aA[mf] + ks * 32);
#pragma unroll
        for (int p = 0; p < NF / 2; ++p) ldsm4(&b[2 * p][0], aB[p] + ks * 32);
#pragma unroll
        for (int mf = 0; mf < MF; ++mf)
#pragma unroll
            for (int nf = 0; nf < NF; ++nf)
                mma_f16(acc[mf][nf], a[mf], b[nf]);
    }
}

template<int MF, int NF>
__device__ __forceinline__ void zacc(float (&a)[MF][NF][4]){
#pragma unroll
    for (int m = 0; m < MF; ++m)
#pragma unroll
        for (int n = 0; n < NF; ++n)
#pragma unroll
            for (int q = 0; q < 4; ++q) a[m][n][q] = 0.f;
}

// relu(acc + bias) -> half smem (stride ldd halves)
template<int MF, int NF>
__device__ __forceinline__ void epi_smem_h(const float (&acc)[MF][NF][4], __half* dst, int ldd,
        const float* __restrict__ bias, int wrow, int wcol, int lane){
    int r0 = wrow + (lane >> 2);
    int c0 = wcol + 2 * (lane & 3);
#pragma unroll
    for (int mf = 0; mf < MF; ++mf)
#pragma unroll
        for (int nf = 0; nf < NF; ++nf){
            int c = c0 + nf * 8;
            float bx = bias[c], by = bias[c + 1];
            int ra = r0 + mf * 16, rb = ra + 8;
            *(__half2*)(dst + ra * ldd + c) =
                __floats2half2_rn(fmaxf(acc[mf][nf][0] + bx, 0.f), fmaxf(acc[mf][nf][1] + by, 0.f));
            *(__half2*)(dst + rb * ldd + c) =
                __floats2half2_rn(fmaxf(acc[mf][nf][2] + bx, 0.f), fmaxf(acc[mf][nf][3] + by, 0.f));
        }
}

// dst += relu(acc + bias)
template<int MF, int NF>
__device__ __forceinline__ void epi_add_smem_h(const float (&acc)[MF][NF][4], __half* dst, int ldd,
        const float* __restrict__ bias, int wrow, int wcol, int lane){
    int r0 = wrow + (lane >> 2);
    int c0 = wcol + 2 * (lane & 3);
#pragma unroll
    for (int mf = 0; mf < MF; ++mf)
#pragma unroll
        for (int nf = 0; nf < NF; ++nf){
            int c = c0 + nf * 8;
            float bx = bias[c], by = bias[c + 1];
            int ra = r0 + mf * 16, rb = ra + 8;
            __half2* pa = (__half2*)(dst + ra * ldd + c);
            __half2* pb = (__half2*)(dst + rb * ldd + c);
            float2 oa = __half22float2(*pa), ob = __half22float2(*pb);
            *pa = __floats2half2_rn(oa.x + fmaxf(acc[mf][nf][0] + bx, 0.f),
                                    oa.y + fmaxf(acc[mf][nf][1] + by, 0.f));
            *pb = __floats2half2_rn(ob.x + fmaxf(acc[mf][nf][2] + bx, 0.f),
                                    ob.y + fmaxf(acc[mf][nf][3] + by, 0.f));
        }
}

// relu(acc + bias) -> gmem tile (stride 128 floats)
template<int MF, int NF>
__device__ __forceinline__ void epi_gmem_relu(const float (&acc)[MF][NF][4], float* __restrict__ dst,
        const float* __restrict__ bias, int wrow, int wcol, int lane){
    int r0 = wrow + (lane >> 2);
    int c0 = wcol + 2 * (lane & 3);
#pragma unroll
    for (int mf = 0; mf < MF; ++mf)
#pragma unroll
        for (int nf = 0; nf < NF; ++nf){
            int c = c0 + nf * 8;
            float bx = bias[c], by = bias[c + 1];
            int ra = r0 + mf * 16, rb = ra + 8;
            *(float2*)(dst + ra * 128 + c) = make_float2(fmaxf(acc[mf][nf][0] + bx, 0.f),
                                                         fmaxf(acc[mf][nf][1] + by, 0.f));
            *(float2*)(dst + rb * 128 + c) = make_float2(fmaxf(acc[mf][nf][2] + bx, 0.f),
                                                         fmaxf(acc[mf][nf][3] + by, 0.f));
        }
}
template<int MF, int NF>
__device__ __forceinline__ void epi_gmem_raw(const float (&acc)[MF][NF][4], float* __restrict__ dst,
        int wrow, int wcol, int lane){
    int r0 = wrow + (lane >> 2);
    int c0 = wcol + 2 * (lane & 3);
#pragma unroll
    for (int mf = 0; mf < MF; ++mf)
#pragma unroll
        for (int nf = 0; nf < NF; ++nf){
            int c = c0 + nf * 8;
            int ra = r0 + mf * 16, rb = ra + 8;
            *(float2*)(dst + ra * 128 + c) = make_float2(acc[mf][nf][0], acc[mf][nf][1]);
            *(float2*)(dst + rb * 128 + c) = make_float2(acc[mf][nf][2], acc[mf][nf][3]);
        }
}

// ---------------- weight prep ----------------
__device__ __forceinline__ void wprep(__half* dst, const float* src, int Kpad, int Ksrc, int tid){
    for (int i = tid; i < 128 * Kpad; i += 256){
        int n = i / Kpad, k = i - n * Kpad;
        dst[i] = __float2half_rn(k < Ksrc ? src[k * 128 + n] : 0.f);
    }
}
extern "C" __global__ void kW(const float* __restrict__ p2aW0, const float* __restrict__ p2aW1,
                              const float* __restrict__ p2pW0, const float* __restrict__ p2pW1,
                              const float* __restrict__ a2pW1, const float* __restrict__ plW0,
                              const float* __restrict__ plW1,  const float* __restrict__ alW0,
                              const float* __restrict__ alW1,  const float* __restrict__ a2aW0,
                              const float* __restrict__ a2aW1, const float* __restrict__ a2pW0){
    int t = blockIdx.x, tid = threadIdx.x;
    switch (t){
        case 0:  wprep(g_Wp2a0,  p2aW0,            16, FP,  tid); break;
        case 1:  wprep(g_Wp2a1,  p2aW1,           128, 128, tid); break;
        case 2:  wprep(g_Wp2p0,  p2pW0,            16, FP,  tid); break;
        case 3:  wprep(g_Wp2p1,  p2pW1,           128, 128, tid); break;
        case 4:  wprep(g_Wa2p1,  a2pW1,           128, 128, tid); break;
        case 5:  wprep(g_Wpl0a,  plW0,            128, 128, tid); break;
        case 6:  wprep(g_Wpl0b,  plW0 + 128*128,  128, 128, tid); break;
        case 7:  wprep(g_Wpl1,   plW1,            128, 128, tid); break;
        case 8:  wprep(g_Wal0a,  alW0,            128, 128, tid); break;
        case 9:  wprep(g_Wal0b,  alW0 + 128*128,  128, 128, tid); break;
        case 10: wprep(g_Wal1,   alW1,            128, 128, tid); break;
        case 11: wprep(g_Wa2a0,  a2aW0,            80, FA,  tid); break;
        case 12: wprep(g_Wa2a1,  a2aW1,           128, 128, tid); break;
        case 13: wprep(g_Wa2p0a, a2pW0,            80, FA,  tid); break;
        default: wprep(g_Wa2p0b, a2pW0 + FA*128,   80, FA,  tid); break;
    }
}

// ---------------- kernel A: atom precompute (R8-proven) ----------------
extern "C" __global__ void __launch_bounds__(256, 1)
kA(const float* __restrict__ atom_x,
   const float* __restrict__ a2a_b0, const float* __restrict__ a2a_b1){
    extern __shared__ __half smh[];
    __half* As  = smh;                    // 128*136
    __half* act = As + 128 * 136;         // 128*136
    __half* Bw  = act + 128 * 136;        // 128*136
    int tid = threadIdx.x, lane = tid & 31, w = tid >> 5;
    int wr = (w & 1) * 64, wc = (w >> 1) * 32;
    int blk = blockIdx.x, task = blockIdx.y;
    uint32_t As_a = smem_u32(As), act_a = smem_u32(act), Bw_a = smem_u32(Bw);

    const __half* w0 = (task == 0) ? g_Wa2a0 : (task == 1 ? g_Wa2p0a : g_Wa2p0b);
    cpa_h(Bw, w0, 80, 136, tid, 256);
    for (int i = tid; i < 128 * 80; i += 256){
        int r = i / 80, k = i - r * 80;
        float v = (k < FA) ? atom_x[(blk * 128 + r) * FA + k] : 0.f;
        As[r * 136 + k] = __float2half_rn(v);
    }
    CP_WAIT0;
    __syncthreads();

    float acc[4][4][4];
    zacc(acc);
    wg_ldsm<5, 4, 4>(acc, As_a, 136, Bw_a, 136, wr, wc, lane);
    if (task == 0){
        __syncthreads();
        cpa_h(Bw, g_Wa2a1, 128, 136, tid, 256);
        epi_smem_h<4,4>(acc, act, 136, a2a_b0, wr, wc, lane);
        CP_WAIT0;
        __syncthreads();
        zacc(acc);
        wg_ldsm<8, 4, 4>(acc, act_a, 136, Bw_a, 136, wr, wc, lane);
        epi_gmem_relu<4,4>(acc, g_a0 + blk * 16384, a2a_b1, wr, wc, lane);
    } else {
        float* dst = (task == 1 ? g_U : g_V) + blk * 16384;
        epi_gmem_raw<4,4>(acc, dst, wr, wc, lane);
    }
}

// ---------------- kernel B: fused pair pipeline (R8 structure, PROVEN BEST) ----------------
// grid 2048: CTA per (b,i2); rows r: ih = 2*i2 + (r>>6), j = r&63. 256 threads, 2 CTAs/SM.
extern "C" __global__ void __launch_bounds__(256, 2)
kB(const float* __restrict__ pair_x,
   const float* __restrict__ p2a_b0, const float* __restrict__ p2a_b1,
   const float* __restrict__ p2p_b0, const float* __restrict__ p2p_b1,
   const float* __restrict__ a2p_b0, const float* __restrict__ a2p_b1,
   const float* __restrict__ pl_b0,  const float* __restrict__ pl_b1,
   float* __restrict__ out_pair){
    extern __shared__ __half smh[];
    __half* actA = smh;                   // 128*136
    __half* actB = actA + 128 * 136;      // 128*136
    __half* Bw   = actB + 128 * 136;      // 128*136
    __half* pxs  = Bw + 128 * 136;        // 128*24
    int tid = threadIdx.x, lane = tid & 31, w = tid >> 5;
    int wm = w & 1;
    int wr = wm * 64, wc = (w >> 1) * 32;
    int cta = blockIdx.x;
    int b = cta >> 5, i2 = cta & 31;
    size_t tilebase = (size_t)b * 4096 + (size_t)i2 * 128;
    const float* gU = g_U + b * 8192;
    const float* gV = g_V + b * 8192;
    uint32_t actA_a = smem_u32(actA), actB_a = smem_u32(actB), Bw_a = smem_u32(Bw);
    uint32_t pxs_a = smem_u32(pxs);

    float acc[4][4][4];

    // ---- prologue: p2a W0 + pxs ----
    cpa_h(Bw, g_Wp2a0, 16, 24, tid, 256);
    for (int i = tid; i < 128 * 16; i += 256){
        int r = i >> 4, k = i & 15;
        float v = (k < FP) ? pair_x[(tilebase + r) * FP + k] : 0.f;
        pxs[r * 24 + k] = __float2half_rn(v);
    }
    CP_WAIT0;
    __syncthreads();

    // ---- G1: px @ p2aW0 ----
    zacc(acc);
    wg_ldsm<1, 4, 4>(acc, pxs_a, 24, Bw_a, 24, wr, wc, lane);
    __syncthreads();
    cpa_h(Bw, g_Wp2a1, 128, 136, tid, 256);
    epi_smem_h<4,4>(acc, actA, 136, p2a_b0, wr, wc, lane);
    CP_WAIT0;
    __syncthreads();

    // ---- G2: actA @ p2aW1 ; epi = relu + column-sum -> g_a1 ; build h0 -> actA ----
    zacc(acc);
    wg_ldsm<8, 4, 4>(acc, actA_a, 136, Bw_a, 136, wr, wc, lane);
    __syncthreads();
    cpa_h(Bw, g_Wa2p1, 128, 136, tid, 256);
    {
        int c0 = wc + 2 * (lane & 3);
#pragma unroll
        for (int nf = 0; nf < 4; ++nf){
            int c = c0 + nf * 8;
            float bx = p2a_b1[c], by = p2a_b1[c + 1];
            float s0 = 0.f, s1 = 0.f;
#pragma unroll
            for (int mf = 0; mf < 4; ++mf){
                s0 += fmaxf(acc[mf][nf][0] + bx, 0.f) + fmaxf(acc[mf][nf][2] + bx, 0.f);
                s1 += fmaxf(acc[mf][nf][1] + by, 0.f) + fmaxf(acc[mf][nf][3] + by, 0.f);
            }
#pragma unroll
            for (int off = 4; off < 32; off <<= 1){
                s0 += __shfl_xor_sync(0xFFFFFFFFu, s0, off);
                s1 += __shfl_xor_sync(0xFFFFFFFFu, s1, off);
            }
            if (lane < 4){
                float* gr = g_a1 + ((size_t)b * 64 + i2 * 2 + wm) * 128 + c;
                gr[0] = s0; gr[1] = s1;
            }
        }
    }
    for (int i = tid; i < 128 * 32; i += 256){      // h0 = relu(U[ih] + V[j] + b0a)
        int r = i >> 5, c4 = (i & 31) << 2;
        int ih = i2 * 2 + (r >> 6), j = r & 63;
        float4 uu = *(const float4*)(gU + ih * 128 + c4);
        float4 vv = *(const float4*)(gV + j  * 128 + c4);
        float4 bb = *(const float4*)(a2p_b0 + c4);
        *(__half2*)(actA + r * 136 + c4)     = __floats2half2_rn(fmaxf(uu.x + vv.x + bb.x, 0.f),
                                                                 fmaxf(uu.y + vv.y + bb.y, 0.f));
        *(__half2*)(actA + r * 136 + c4 + 2) = __floats2half2_rn(fmaxf(uu.z + vv.z + bb.z, 0.f),
                                                                 fmaxf(uu.w + vv.w + bb.w, 0.f));
    }
    CP_WAIT0;
    __syncthreads();

    // ---- G3: h0 @ a2pW1 (y0) ; epi relu -> actB ; build h1 -> actA ----
    zacc(acc);
    wg_ldsm<8, 4, 4>(acc, actA_a, 136, Bw_a, 136, wr, wc, lane);
    __syncthreads();
    epi_smem_h<4,4>(acc, actB, 136, a2p_b1, wr, wc, lane);
    for (int i = tid; i < 128 * 32; i += 256){      // h1 = relu(U[j] + V[ih] + b0a)
        int r = i >> 5, c4 = (i & 31) << 2;
        int ih = i2 * 2 + (r >> 6), j = r & 63;
        float4 uu = *(const float4*)(gU + j  * 128 + c4);
        float4 vv = *(const float4*)(gV + ih * 128 + c4);
        float4 bb = *(const float4*)(a2p_b0 + c4);
        *(__half2*)(actA + r * 136 + c4)     = __floats2half2_rn(fmaxf(uu.x + vv.x + bb.x, 0.f),
                                                                 fmaxf(uu.y + vv.y + bb.y, 0.f));
        *(__half2*)(actA + r * 136 + c4 + 2) = __floats2half2_rn(fmaxf(uu.z + vv.z + bb.z, 0.f),
                                                                 fmaxf(uu.w + vv.w + bb.w, 0.f));
    }
    __syncthreads();    // Bw still holds a2pW1 — reused

    // ---- G4: h1 @ a2pW1 (y1) ; epi: actB += relu -> actB = p0 ----
    zacc(acc);
    wg_ldsm<8, 4, 4>(acc, actA_a, 136, Bw_a, 136, wr, wc, lane);
    __syncthreads();
    cpa_h(Bw, g_Wp2p0, 16, 24, tid, 256);
    epi_add_smem_h<4,4>(acc, actB, 136, a2p_b1, wr, wc, lane);
    CP_WAIT0;
    __syncthreads();

    // ---- G5: px @ p2pW0 ----
    zacc(acc);
    wg_ldsm<1, 4, 4>(acc, pxs_a, 24, Bw_a, 24, wr, wc, lane);
    __syncthreads();
    cpa_h(Bw, g_Wp2p1, 128, 136, tid, 256);
    epi_smem_h<4,4>(acc, actA, 136, p2p_b0, wr, wc, lane);
    CP_WAIT0;
    __syncthreads();

    // ---- G6: actA @ p2pW1 ; epi relu -> actA = p1 ----
    zacc(acc);
    wg_ldsm<8, 4, 4>(acc, actA_a, 136, Bw_a, 136, wr, wc, lane);
    __syncthreads();
    cpa_h(Bw, g_Wpl0b, 128, 136, tid, 256);
    epi_smem_h<4,4>(acc, actA, 136, p2p_b1, wr, wc, lane);
    CP_WAIT0;
    __syncthreads();

    // ---- G7: p1 @ plW0b (no epilogue) ----
    zacc(acc);
    wg_ldsm<8, 4, 4>(acc, actA_a, 136, Bw_a, 136, wr, wc, lane);
    __syncthreads();
    cpa_h(Bw, g_Wpl0a, 128, 136, tid, 256);
    CP_WAIT0;
    __syncthreads();

    // ---- G8: acc += p0 @ plW0a ; epi relu -> actA ----
    wg_ldsm<8, 4, 4>(acc, actB_a, 136, Bw_a, 136, wr, wc, lane);
    __syncthreads();
    cpa_h(Bw, g_Wpl1, 128, 136, tid, 256);
    epi_smem_h<4,4>(acc, actA, 136, pl_b0, wr, wc, lane);
    CP_WAIT0;
    __syncthreads();

    // ---- G9: actA @ plW1 -> out ----
    zacc(acc);
    wg_ldsm<8, 4, 4>(acc, actA_a, 136, Bw_a, 136, wr, wc, lane);
    epi_gmem_relu<4,4>(acc, out_pair + tilebase * 128, pl_b1, wr, wc, lane);
}

// ---------------- kernel C: atom finalize, grid 128 (M=32 per CTA, R14-proven) ----------------
extern "C" __global__ void __launch_bounds__(256, 2)
kC(const float* __restrict__ al_b0, const float* __restrict__ al_b1,
   float* __restrict__ out_atom){
    extern __shared__ __half smh[];
    __half* As  = smh;                    // 32*136
    __half* Bw0 = As + 32 * 136;          // 128*136
    __half* Bw1 = Bw0 + 128 * 136;        // 128*136
    int tid = threadIdx.x, lane = tid & 31, w = tid >> 5;
    int blk = blockIdx.x;
    int base = (blk >> 1) * 8192 + (blk & 1) * 4096;
    uint32_t As_a = smem_u32(As), B0_a = smem_u32(Bw0), B1_a = smem_u32(Bw1);
    const int wc = w * 16;

    cpa_h(Bw0, g_Wal0a, 128, 136, tid, 256);
    cpa_h(Bw1, g_Wal0b, 128, 136, tid, 256);
    for (int i = tid; i < 32 * 32; i += 256){
        int r = i >> 5, c4 = (i & 31) << 2;
        float4 v = *(const float4*)(g_a0 + base + r * 128 + c4);
        *(__half2*)(As + r * 136 + c4)     = __floats2half2_rn(v.x, v.y);
        *(__half2*)(As + r * 136 + c4 + 2) = __floats2half2_rn(v.z, v.w);
    }
    CP_WAIT1;
    __syncthreads();

    float acc[2][2][4];
    zacc(acc);
    wg_ldsm<8, 2, 2>(acc, As_a, 136, B0_a, 136, 0, wc, lane);
    __syncthreads();
    cpa_h(Bw0, g_Wal1, 128, 136, tid, 256);
    for (int i = tid; i < 32 * 32; i += 256){
        int r = i >> 5, c4 = (i & 31) << 2;
        float4 v = *(const float4*)(g_a1 + base + r * 128 + c4);
        *(__half2*)(As + r * 136 + c4)     = __floats2half2_rn(v.x, v.y);
        *(__half2*)(As + r * 136 + c4 + 2) = __floats2half2_rn(v.z, v.w);
    }
    CP_WAIT1;
    __syncthreads();

    wg_ldsm<8, 2, 2>(acc, As_a, 136, B1_a, 136, 0, wc, lane);
    __syncthreads();
    epi_smem_h<2,2>(acc, As, 136, al_b0, 0, wc, lane);
    CP_WAIT0;
    __syncthreads();

    zacc(acc);
    wg_ldsm<8, 2, 2>(acc, As_a, 136, B0_a, 136, 0, wc, lane);
    epi_gmem_relu<2,2>(acc, out_atom + base, al_b1, 0, wc, lane);
}

// ---------------------------------------------------------------------------
extern "C" void kernel_launch(void* const* d_in, const int* in_sizes, int n_in,
                              void* d_out, int out_size) {
    const float* atom_x = (const float*)d_in[0];
    const float* pair_x = (const float*)d_in[1];
    const float* a2a_W0 = (const float*)d_in[2];
    const float* a2a_b0 = (const float*)d_in[3];
    const float* a2a_W1 = (const float*)d_in[4];
    const float* a2a_b1 = (const float*)d_in[5];
    const float* p2a_W0 = (const float*)d_in[6];
    const float* p2a_b0 = (const float*)d_in[7];
    const float* p2a_W1 = (const float*)d_in[8];
    const float* p2a_b1 = (const float*)d_in[9];
    const float* al_W0  = (const float*)d_in[10];
    const float* al_b0  = (const float*)d_in[11];
    const float* al_W1  = (const float*)d_in[12];
    const float* al_b1  = (const float*)d_in[13];
    const float* a2p_W0 = (const float*)d_in[14];
    const float* a2p_b0 = (const float*)d_in[15];
    const float* a2p_W1 = (const float*)d_in[16];
    const float* a2p_b1 = (const float*)d_in[17];
    const float* p2p_W0 = (const float*)d_in[18];
    const float* p2p_b0 = (const float*)d_in[19];
    const float* p2p_W1 = (const float*)d_in[20];
    const float* p2p_b1 = (const float*)d_in[21];
    const float* pl_W0  = (const float*)d_in[22];
    const float* pl_b0  = (const float*)d_in[23];
    const float* pl_W1  = (const float*)d_in[24];
    const float* pl_b1  = (const float*)d_in[25];
    float* out = (float*)d_out;

    const int SMEM_A = (3 * 128 * 136) * 2;                 // 104448 B
    const int SMEM_B = (3 * 128 * 136 + 128 * 24) * 2;      // 110592 B
    const int SMEM_C = (32 * 136 + 2 * 128 * 136) * 2;      // 78336 B

    cudaFuncSetAttribute(kA, cudaFuncAttributeMaxDynamicSharedMemorySize, SMEM_A);
    cudaFuncSetAttribute(kB, cudaFuncAttributeMaxDynamicSharedMemorySize, SMEM_B);
    cudaFuncSetAttribute(kC, cudaFuncAttributeMaxDynamicSharedMemorySize, SMEM_C);

    kW<<<15, 256>>>(p2a_W0, p2a_W1, p2p_W0, p2p_W1, a2p_W1, pl_W0, pl_W1,
                    al_W0, al_W1, a2a_W0, a2a_W1, a2p_W0);
    kA<<<dim3(32, 3), 256, SMEM_A>>>(atom_x, a2a_b0, a2a_b1);
    kB<<<2048, 256, SMEM_B>>>(pair_x,
                              p2a_b0, p2a_b1, p2p_b0, p2p_b1,
                              a2p_b0, a2p_b1, pl_b0, pl_b1,
                              out + ATOM_OUT);
    kC<<<128, 256, SMEM_C>>>(al_b0, al_b1, out);
}